// round 6
// baseline (speedup 1.0000x reference)
#include <cuda_runtime.h>
#include <math.h>

#define BB 256
#define SS 512
#define EE 128
#define HH 256
#define NCOL 8
#define NJT 16
#define BT 32
#define WSP 68
#define HSP 260
#define GSP 68

// device scratch (no allocations allowed)
__device__ float g_enc_out[BB * SS * HH];   // encoder hidden states, also h feed
__device__ float g_hbuf[2 * BB * HH];       // process-block h ping-pong
__device__ float g_M[1024 * 2];             // enc_Wih @ W_emb
__device__ float g_bias[1024];              // enc_bih + enc_bhh
__device__ float g_xp[1024];                // pb_Wih @ dec_input + pb biases
__device__ float g_q[BB * HH];
__device__ float g_u[BB * SS];
__device__ int   g_cnt[NCOL * 1024];

__device__ __forceinline__ float sigf(float x) { return 1.0f / (1.0f + expf(-x)); }

// ------------------- init: fold small matrices, zero counters -------------------
__global__ void init_kernel(const float* __restrict__ encWih, const float* __restrict__ Wemb,
                            const float* __restrict__ encBih, const float* __restrict__ encBhh,
                            const float* __restrict__ pbWih,  const float* __restrict__ decIn,
                            const float* __restrict__ pbBih,  const float* __restrict__ pbBhh)
{
    int r = blockIdx.x * blockDim.x + threadIdx.x;
    if (r >= 1024) return;
    float m0 = 0.f, m1 = 0.f, xp = 0.f;
    for (int e = 0; e < EE; e++) {
        float w = encWih[r * EE + e];
        m0 = fmaf(w, Wemb[e * 2 + 0], m0);
        m1 = fmaf(w, Wemb[e * 2 + 1], m1);
        xp = fmaf(pbWih[r * EE + e], decIn[e], xp);
    }
    g_M[2 * r] = m0; g_M[2 * r + 1] = m1;
    g_bias[r] = encBih[r] + encBhh[r];
    g_xp[r]   = xp + pbBih[r] + pbBhh[r];
#pragma unroll
    for (int q = 0; q < 8; q++) g_cnt[r * 8 + q] = 0;
}

// load 64 Whh rows (gate-interleaved mapping) transposed: ws[k*WSP+r] = W[grow(r)][k]
__device__ __forceinline__ void load_w(float* ws, const float* __restrict__ W, int j0, int tid)
{
    int r = tid >> 2;
    int grow = (r >> 4) * HH + j0 + (r & 15);
    int ks = (tid & 3) << 6;
    const float4* src = (const float4*)(W + grow * HH + ks);
#pragma unroll
    for (int q = 0; q < 16; q++) {
        float4 v = src[q];
        int k = ks + q * 4;
        ws[(k + 0) * WSP + r] = v.x;
        ws[(k + 1) * WSP + r] = v.y;
        ws[(k + 2) * WSP + r] = v.z;
        ws[(k + 3) * WSP + r] = v.w;
    }
}

// load 64 straight rows [j0..j0+63] transposed
__device__ __forceinline__ void load_wrows(float* ws, const float* __restrict__ W, int j0, int tid)
{
    int r = tid >> 2;
    int ks = (tid & 3) << 6;
    const float4* src = (const float4*)(W + (j0 + r) * HH + ks);
#pragma unroll
    for (int q = 0; q < 16; q++) {
        float4 v = src[q];
        int k = ks + q * 4;
        ws[(k + 0) * WSP + r] = v.x;
        ws[(k + 1) * WSP + r] = v.y;
        ws[(k + 2) * WSP + r] = v.z;
        ws[(k + 3) * WSP + r] = v.w;
    }
}

// ------------------- persistent LSTM kernel: encoder then process block -------------------
__global__ void __launch_bounds__(256, 1)
lstm_kernel(const float* __restrict__ inp,
            const float* __restrict__ encWhh,
            const float* __restrict__ pbWhh)
{
    extern __shared__ float sm[];
    float* ws  = sm;                 // [256][WSP]
    float* hs  = ws + 256 * WSP;     // [32][HSP]
    float* gs  = hs + 32 * HSP;      // [32][GSP]
    float* cs  = gs + 32 * GSP;      // [512]
    float* msx = cs + 512;           // [64]
    float* msy = msx + 64;
    float* msb = msy + 64;
    float* xin = msb + 64;           // [64]
    float* xps = xin + 64;           // [64]

    const int tid = threadIdx.x;
    const int col = blockIdx.x & 7;
    const int jt  = blockIdx.x >> 3;
    const int b0g = col * BT;
    const int j0  = jt * 16;

    if (tid < 64) {
        int grow = (tid >> 4) * HH + j0 + (tid & 15);
        msx[tid] = g_M[2 * grow];
        msy[tid] = g_M[2 * grow + 1];
        msb[tid] = g_bias[grow];
        xps[tid] = g_xp[grow];
    }
    cs[tid] = 0.f; cs[tid + 256] = 0.f;
    load_w(ws, encWhh, j0, tid);

    const int jg = tid & 15;
    const int bg = tid >> 4;
    const int r0 = jg * 4;
    const int bb = bg * 2;

    for (int step = 0; step < 1024; step++) {
        const bool enc = step < 512;
        if (step == 512) {
            __syncthreads();
            load_w(ws, pbWhh, j0, tid);
        }

        if (step >= 1) {
            if (tid == 0) {
                volatile int* cp = &g_cnt[col * 1024 + step - 1];
                while (*cp < NJT) __nanosleep(32);
            }
            __syncthreads();
            __threadfence();
#pragma unroll
            for (int it = 0; it < 8; it++) {
                int i = tid + it * 256;
                int b = i >> 6;
                int kq = (i & 63) << 2;
                const float* src = (step <= 512)
                    ? (g_enc_out + (((size_t)(b0g + b) * SS + (step - 1)) * HH + kq))
                    : (g_hbuf + ((size_t)((step - 513) & 1)) * BB * HH + (size_t)(b0g + b) * HH + kq);
                float4 v = __ldcg((const float4*)src);
                *(float4*)(hs + b * HSP + kq) = v;
            }
        }
        if (enc && tid < 64) {
            int b = tid >> 1;
            xin[tid] = inp[((size_t)(b0g + b) * SS + step) * 2 + (tid & 1)];
        }
        __syncthreads();

        float acc0[4] = {0.f, 0.f, 0.f, 0.f};
        float acc1[4] = {0.f, 0.f, 0.f, 0.f};
        if (step >= 1) {
            const float* hp0 = hs + bb * HSP;
            const float* hp1 = hp0 + HSP;
            const float* wp  = ws + r0;
#pragma unroll 8
            for (int k = 0; k < HH; k += 4) {
                float4 h04 = *(const float4*)(hp0 + k);
                float4 h14 = *(const float4*)(hp1 + k);
                float h0a[4] = {h04.x, h04.y, h04.z, h04.w};
                float h1a[4] = {h14.x, h14.y, h14.z, h14.w};
#pragma unroll
                for (int kk = 0; kk < 4; kk++) {
                    float4 w4 = *(const float4*)(wp + (k + kk) * WSP);
                    float wa[4] = {w4.x, w4.y, w4.z, w4.w};
#pragma unroll
                    for (int j = 0; j < 4; j++) {
                        acc0[j] = fmaf(h0a[kk], wa[j], acc0[j]);
                        acc1[j] = fmaf(h1a[kk], wa[j], acc1[j]);
                    }
                }
            }
        }
        *(float4*)(gs + bb * GSP + r0)       = make_float4(acc0[0], acc0[1], acc0[2], acc0[3]);
        *(float4*)(gs + (bb + 1) * GSP + r0) = make_float4(acc1[0], acc1[1], acc1[2], acc1[3]);
        __syncthreads();

        // elementwise cell: 512 (b,jj) pairs, 2 per thread
#pragma unroll
        for (int pp = 0; pp < 2; pp++) {
            int p = tid + pp * 256;
            int b = p >> 4, jj = p & 15;
            float gi = gs[b * GSP + jj];
            float gf = gs[b * GSP + 16 + jj];
            float gg = gs[b * GSP + 32 + jj];
            float go = gs[b * GSP + 48 + jj];
            if (enc) {
                float x0 = xin[b * 2], x1 = xin[b * 2 + 1];
                gi += fmaf(msx[jj],      x0, fmaf(msy[jj],      x1, msb[jj]));
                gf += fmaf(msx[16 + jj], x0, fmaf(msy[16 + jj], x1, msb[16 + jj]));
                gg += fmaf(msx[32 + jj], x0, fmaf(msy[32 + jj], x1, msb[32 + jj]));
                go += fmaf(msx[48 + jj], x0, fmaf(msy[48 + jj], x1, msb[48 + jj]));
            } else {
                gi += xps[jj]; gf += xps[16 + jj]; gg += xps[32 + jj]; go += xps[48 + jj];
            }
            float c = cs[p];
            c = sigf(gf) * c + sigf(gi) * tanhf(gg);
            float h = sigf(go) * tanhf(c);
            cs[p] = c;
            if (enc)
                g_enc_out[((size_t)(b0g + b) * SS + step) * HH + j0 + jj] = h;
            else
                g_hbuf[((size_t)((step - 512) & 1)) * BB * HH + (size_t)(b0g + b) * HH + j0 + jj] = h;
        }
        __threadfence();
        __syncthreads();
        if (tid == 0) atomicAdd(&g_cnt[col * 1024 + step], 1);
    }
}

// ------------------- q = h_final @ Wq^T + bq -------------------
__global__ void qproj_kernel(const float* __restrict__ Wq, const float* __restrict__ bq)
{
    __shared__ float hb[HH];
    int b = blockIdx.x, j = threadIdx.x;
    hb[j] = g_hbuf[(size_t)BB * HH + (size_t)b * HH + j];  // final pb h is in slot 1
    __syncthreads();
    float a = bq[j];
    const float* w = Wq + (size_t)j * HH;
#pragma unroll 8
    for (int k = 0; k < HH; k++) a = fmaf(hb[k], w[k], a);
    g_q[(size_t)b * HH + j] = a;
}

// ------------------- u[b,s] = sum_j V[j] * tanh(enc@Wref^T + bref + q) -------------------
__global__ void __launch_bounds__(256, 2)
attnU_kernel(const float* __restrict__ Wref, const float* __restrict__ bref,
             const float* __restrict__ V)
{
    extern __shared__ float sm[];
    float* wt = sm;                 // [256][WSP]
    float* es = wt + 256 * WSP;     // [32][HSP]
    float* us = es + 32 * HSP;      // [32][17]

    const int tid = threadIdx.x;
    const int b  = blockIdx.y;
    const int s0 = blockIdx.x * 32;
    const int jg = tid & 15;
    const int bg = tid >> 4;
    const int r0 = jg * 4;
    const int ss = bg * 2;

#pragma unroll
    for (int it = 0; it < 8; it++) {
        int i = tid + it * 256;
        int s = i >> 6;
        int kq = (i & 63) << 2;
        float4 v = __ldcg((const float4*)(g_enc_out + ((size_t)b * SS + s0 + s) * HH + kq));
        *(float4*)(es + s * HSP + kq) = v;
    }

    float u0 = 0.f, u1 = 0.f;
    for (int jt = 0; jt < 4; jt++) {
        __syncthreads();
        load_wrows(wt, Wref, jt * 64, tid);
        __syncthreads();

        float acc0[4] = {0.f, 0.f, 0.f, 0.f};
        float acc1[4] = {0.f, 0.f, 0.f, 0.f};
        const float* hp0 = es + ss * HSP;
        const float* hp1 = hp0 + HSP;
        const float* wp  = wt + r0;
#pragma unroll 8
        for (int k = 0; k < HH; k += 4) {
            float4 h04 = *(const float4*)(hp0 + k);
            float4 h14 = *(const float4*)(hp1 + k);
            float h0a[4] = {h04.x, h04.y, h04.z, h04.w};
            float h1a[4] = {h14.x, h14.y, h14.z, h14.w};
#pragma unroll
            for (int kk = 0; kk < 4; kk++) {
                float4 w4 = *(const float4*)(wp + (k + kk) * WSP);
                float wa[4] = {w4.x, w4.y, w4.z, w4.w};
#pragma unroll
                for (int j = 0; j < 4; j++) {
                    acc0[j] = fmaf(h0a[kk], wa[j], acc0[j]);
                    acc1[j] = fmaf(h1a[kk], wa[j], acc1[j]);
                }
            }
        }
#pragma unroll
        for (int m = 0; m < 4; m++) {
            int j = jt * 64 + r0 + m;
            float addv = __ldg(bref + j) + g_q[(size_t)b * HH + j];
            float vv = __ldg(V + j);
            u0 += tanhf(acc0[m] + addv) * vv;
            u1 += tanhf(acc1[m] + addv) * vv;
        }
    }
    us[ss * 17 + jg]       = u0;
    us[(ss + 1) * 17 + jg] = u1;
    __syncthreads();
    if (tid < 32) {
        float t = 0.f;
#pragma unroll
        for (int q = 0; q < 16; q++) t += us[tid * 17 + q];
        g_u[(size_t)b * SS + s0 + tid] = t;
    }
}

// ------------------- softmax + glimpse + head -------------------
__global__ void final_kernel(const float* __restrict__ Wd1, const float* __restrict__ Wd2,
                             float* __restrict__ out)
{
    __shared__ float al[SS];
    __shared__ float red[8];
    __shared__ float gb[HH];
    int b = blockIdx.x, tid = threadIdx.x;
    int lane = tid & 31, wid = tid >> 5;

    float u0 = g_u[(size_t)b * SS + tid];
    float u1 = g_u[(size_t)b * SS + 256 + tid];

    float m = fmaxf(u0, u1);
#pragma unroll
    for (int o = 16; o > 0; o >>= 1) m = fmaxf(m, __shfl_xor_sync(0xffffffffu, m, o));
    if (lane == 0) red[wid] = m;
    __syncthreads();
    float M2 = red[0];
#pragma unroll
    for (int w = 1; w < 8; w++) M2 = fmaxf(M2, red[w]);
    __syncthreads();

    float e0 = expf(u0 - M2), e1 = expf(u1 - M2);
    al[tid] = e0; al[tid + 256] = e1;
    float s = e0 + e1;
#pragma unroll
    for (int o = 16; o > 0; o >>= 1) s += __shfl_xor_sync(0xffffffffu, s, o);
    if (lane == 0) red[wid] = s;
    __syncthreads();
    float Ssum = 0.f;
#pragma unroll
    for (int w = 0; w < 8; w++) Ssum += red[w];
    __syncthreads();

    // glimpse: thread -> hidden dim
    float a0 = 0.f, a1 = 0.f, a2 = 0.f, a3 = 0.f;
    const float* ep = g_enc_out + (size_t)b * SS * HH + tid;
    for (int sIdx = 0; sIdx < SS; sIdx += 4) {
        a0 = fmaf(al[sIdx + 0], __ldcg(ep + (size_t)(sIdx + 0) * HH), a0);
        a1 = fmaf(al[sIdx + 1], __ldcg(ep + (size_t)(sIdx + 1) * HH), a1);
        a2 = fmaf(al[sIdx + 2], __ldcg(ep + (size_t)(sIdx + 2) * HH), a2);
        a3 = fmaf(al[sIdx + 3], __ldcg(ep + (size_t)(sIdx + 3) * HH), a3);
    }
    gb[tid] = ((a0 + a1) + (a2 + a3)) / Ssum;
    __syncthreads();

    // head: t_j = relu(g @ Wd1[j]) * Wd2[j]; out = sum_j t_j
    float t = 0.f;
    const float* w1 = Wd1 + (size_t)tid * HH;
#pragma unroll 8
    for (int k = 0; k < HH; k++) t = fmaf(gb[k], w1[k], t);
    t = fmaxf(t, 0.f) * __ldg(Wd2 + tid);
#pragma unroll
    for (int o = 16; o > 0; o >>= 1) t += __shfl_xor_sync(0xffffffffu, t, o);
    if (lane == 0) red[wid] = t;
    __syncthreads();
    if (tid == 0) {
        float r = 0.f;
#pragma unroll
        for (int w = 0; w < 8; w++) r += red[w];
        out[b] = r;
    }
}

extern "C" void kernel_launch(void* const* d_in, const int* in_sizes, int n_in,
                              void* d_out, int out_size)
{
    const float* inp    = (const float*)d_in[0];
    const float* Wemb   = (const float*)d_in[1];
    const float* decIn  = (const float*)d_in[2];
    const float* encWih = (const float*)d_in[3];
    const float* encWhh = (const float*)d_in[4];
    const float* encBih = (const float*)d_in[5];
    const float* encBhh = (const float*)d_in[6];
    const float* pbWih  = (const float*)d_in[7];
    const float* pbWhh  = (const float*)d_in[8];
    const float* pbBih  = (const float*)d_in[9];
    const float* pbBhh  = (const float*)d_in[10];
    const float* Wq     = (const float*)d_in[11];
    const float* bq     = (const float*)d_in[12];
    const float* Wref   = (const float*)d_in[13];
    const float* bref   = (const float*)d_in[14];
    const float* V      = (const float*)d_in[15];
    const float* Wd1    = (const float*)d_in[16];
    const float* Wd2    = (const float*)d_in[17];

    const int LSTM_SMEM = (256 * WSP + 32 * HSP + 32 * GSP + 512 + 64 * 5) * 4;  // 114944
    const int ATTN_SMEM = (256 * WSP + 32 * HSP + 32 * 17) * 4;                   // 105088

    cudaFuncSetAttribute(lstm_kernel,  cudaFuncAttributeMaxDynamicSharedMemorySize, LSTM_SMEM);
    cudaFuncSetAttribute(attnU_kernel, cudaFuncAttributeMaxDynamicSharedMemorySize, ATTN_SMEM);

    init_kernel<<<4, 256>>>(encWih, Wemb, encBih, encBhh, pbWih, decIn, pbBih, pbBhh);
    lstm_kernel<<<NCOL * NJT, 256, LSTM_SMEM>>>(inp, encWhh, pbWhh);
    qproj_kernel<<<BB, 256>>>(Wq, bq);
    attnU_kernel<<<dim3(SS / 32, BB), 256, ATTN_SMEM>>>(Wref, bref, V);
    final_kernel<<<BB, 256>>>(Wd1, Wd2, (float*)d_out);
}